// round 11
// baseline (speedup 1.0000x reference)
#include <cuda_runtime.h>
#include <cuda_bf16.h>
#include <cstdint>

// ---------------- problem constants ----------------
#define NCH      4
#define LL       4608          // L = nH*nW
#define NW       576           // nW
#define TM       64            // M tile (attn rows per CTA)
#define KC       64            // bf16 K elements per pipeline chunk
#define NCHUNKS  72            // 4608 / 64
#define BNROWS   96            // N padded (81 -> 96)
#define WPITCH   5184          // 72*72
#define XCH      373248        // 72*5184 elements per channel
#define NBLK_M   72            // 4608/64
#define PITCH    144           // padded row pitch (bytes): conflict-free, no swizzle

// ---------------- smem layout (bytes), 4-stage ----------------
#define SM_NZ       0
#define SM_A(s)     (512   + (s)*9216)      // 64 rows x 144B, 4 stages
#define SM_B(s)     (37376 + (s)*13824)     // 96 rows x 144B, 4 stages
#define SM_RED      512                     // acc exchange region (reuses A stages)
#define SMEM_BYTES  92672

// ---------------- scratch: patches bf16, K-major, padded to 96 rows ----------------
__device__ __nv_bfloat16 g_Bmat[(size_t)NCH * BNROWS * LL];

__device__ __forceinline__ uint32_t smem_to_u32(const void* p) {
    uint32_t a;
    asm("{ .reg .u64 t; cvta.to.shared.u64 t, %1; cvt.u32.u64 %0, t; }" : "=r"(a) : "l"(p));
    return a;
}

__device__ __forceinline__ void ldmx4(uint32_t* r, uint32_t addr) {
    asm volatile("ldmatrix.sync.aligned.m8n8.x4.shared.b16 {%0,%1,%2,%3}, [%4];"
                 : "=r"(r[0]), "=r"(r[1]), "=r"(r[2]), "=r"(r[3]) : "r"(addr));
}
__device__ __forceinline__ void ldmx2(uint32_t* r, uint32_t addr) {
    asm volatile("ldmatrix.sync.aligned.m8n8.x2.shared.b16 {%0,%1}, [%2];"
                 : "=r"(r[0]), "=r"(r[1]) : "r"(addr));
}

__device__ __forceinline__ void mma16816(float* d, const uint32_t* a,
                                         uint32_t b0, uint32_t b1) {
    asm volatile(
        "mma.sync.aligned.m16n8k16.row.col.f32.bf16.bf16.f32 "
        "{%0,%1,%2,%3}, {%4,%5,%6,%7}, {%8,%9}, {%0,%1,%2,%3};"
        : "+f"(d[0]), "+f"(d[1]), "+f"(d[2]), "+f"(d[3])
        : "r"(a[0]), "r"(a[1]), "r"(a[2]), "r"(a[3]), "r"(b0), "r"(b1));
}

#define CP_ASYNC_CG(dst, src) \
    asm volatile("cp.async.cg.shared.global [%0], [%1], 16;" :: "r"(dst), "l"(src))
#define CP_COMMIT() asm volatile("cp.async.commit_group;" ::: "memory")
#define CP_WAIT(n)  asm volatile("cp.async.wait_group %0;" :: "n"(n) : "memory")

// ---------------- prep kernel: fold x -> bf16 patches (K-major, 96 rows) ----------------
__global__ void build_b_kernel(const float* __restrict__ x) {
    int idx = blockIdx.x * blockDim.x + threadIdx.x;  // 6912*256 = 4*96*4608
    int m = idx % LL;
    int k = (idx / LL) % BNROWS;
    int c = idx / (LL * BNROWS);
    float v = 0.0f;
    if (k < 81) {
        int bi = m / NW, bj = m % NW;
        int ki = k / 9,  kj = k % 9;
        v = x[(size_t)c * XCH + (size_t)(bi * 9 + ki) * WPITCH + (bj * 9 + kj)];
    }
    g_Bmat[idx] = __float2bfloat16(v);
}

// ---------------- main fused kernel ----------------
__global__ void __launch_bounds__(256, 2) cross_head_main(
    const float* __restrict__ attn,
    const float* __restrict__ x,
    float* __restrict__ out)
{
    extern __shared__ char smem[];
    const uint32_t sbase = smem_to_u32(smem);
    const int tid  = threadIdx.x;
    const int wid  = tid >> 5;
    const int lane = tid & 31;
    const int c    = blockIdx.x / NBLK_M;
    const int mb   = blockIdx.x % NBLK_M;

    // phase stagger: odd CTAs start their chunk sweep half-way round
    const int start = (blockIdx.x & 1) * (NCHUNKS / 2);

    // warp tile: 2m x 2n x 2k split; each warp m32 x n48 x half the k-steps
    const int kg    = wid >> 2;                // k-group 0/1
    const int mbase = ((wid >> 1) & 1) * 32;
    const int nbase = (wid & 1) * 48;
    const bool nfull = (nbase == 0);           // nbase=48: third tile has only n80 valid

    // ---- producer addressing: thread owns 32B (8 floats) x 2 rows per chunk ----
    const int r0  = tid >> 3;                  // 0..31; rows r0, r0+32
    const int seg = tid & 7;                   // 32B segment within 64-col chunk
    const float* gA0 = attn + ((size_t)c * LL + (size_t)(mb * TM + r0)) * LL + seg * 8;
    const __nv_bfloat16* gB = g_Bmat + (size_t)c * BNROWS * LL;

    // A STS offsets within a stage (pitch-144, conflict-free)
    uint32_t aSts[2];
    #pragma unroll
    for (int g = 0; g < 2; g++)
        aSts[g] = (uint32_t)((r0 + 32 * g) * PITCH + seg * 16);

    // B cp.async indices: 3 x 16B per thread per chunk (96 rows x 8 segs = 768)
    int brow_[3];
    uint32_t bSts[3];
    #pragma unroll
    for (int j = 0; j < 3; j++) {
        int idx = tid + j * 256;               // 0..767
        brow_[j] = idx >> 3;
        bSts[j]  = (uint32_t)(brow_[j] * PITCH + (idx & 7) * 16);
    }

    // ---- ldmatrix lane addressing (pitch-144, no xor) ----
    const int la_row = (lane & 7) + ((lane >> 3) & 1) * 8;
    const int la_col = (lane >> 4) * 16;                       // byte
    uint32_t aBase[2];
    #pragma unroll
    for (int mi = 0; mi < 2; mi++)
        aBase[mi] = (uint32_t)((mbase + 16 * mi + la_row) * PITCH) + (uint32_t)la_col;
    const int lb_n   = (lane & 7) + (lane >> 4) * 8;
    const int lb_col = ((lane >> 3) & 1) * 16;                 // byte
    uint32_t bBase[2];
    #pragma unroll
    for (int j2 = 0; j2 < 2; j2++)
        bBase[j2] = (uint32_t)((nbase + 16 * j2 + lb_n) * PITCH) + (uint32_t)lb_col;
    // third tile: x4 form (full) and x2 form (n-half, lanes 0-15 give addrs)
    const uint32_t bBase4_t2 = (uint32_t)((nbase + 32 + lb_n) * PITCH) + (uint32_t)lb_col;
    const uint32_t bBase2_t2 = (uint32_t)((nbase + 32 + (lane & 7)) * PITCH)
                             + (uint32_t)(((lane >> 3) & 1) * 16);

    // 48 accumulators: [mi][nj(6 n8-tiles)][4]
    float acc[2][6][4];
    #pragma unroll
    for (int mi = 0; mi < 2; mi++)
        #pragma unroll
        for (int nj = 0; nj < 6; nj++)
            #pragma unroll
            for (int r = 0; r < 4; r++) acc[mi][nj][r] = 0.0f;

    int cnt[2] = {0, 0};

    auto mapc = [&](int ch) -> int {           // virtual chunk -> real chunk
        int r = ch + start;
        return (r >= NCHUNKS) ? r - NCHUNKS : r;
    };

    auto sts_count = [&](float4 (&rs)[4], uint32_t saStage) {
        #pragma unroll
        for (int g = 0; g < 2; g++) {
            float4 v0 = rs[2 * g], v1 = rs[2 * g + 1];
            cnt[g] += (v0.x != 0.0f) + (v0.y != 0.0f) + (v0.z != 0.0f) + (v0.w != 0.0f)
                    + (v1.x != 0.0f) + (v1.y != 0.0f) + (v1.z != 0.0f) + (v1.w != 0.0f);
            uint4 p;
            asm("cvt.rn.bf16x2.f32 %0, %1, %2;" : "=r"(p.x) : "f"(v0.y), "f"(v0.x));
            asm("cvt.rn.bf16x2.f32 %0, %1, %2;" : "=r"(p.y) : "f"(v0.w), "f"(v0.z));
            asm("cvt.rn.bf16x2.f32 %0, %1, %2;" : "=r"(p.z) : "f"(v1.y), "f"(v1.x));
            asm("cvt.rn.bf16x2.f32 %0, %1, %2;" : "=r"(p.w) : "f"(v1.w), "f"(v1.z));
            asm volatile("st.shared.v4.b32 [%0], {%1,%2,%3,%4};"
                         :: "r"(saStage + aSts[g]), "r"(p.x), "r"(p.y), "r"(p.z), "r"(p.w));
        }
    };
    auto ldg_a = [&](int vch, float4 (&rl)[4]) {
        const int rc = mapc(vch);
        #pragma unroll
        for (int g = 0; g < 2; g++) {
            const float4* pa = reinterpret_cast<const float4*>(
                gA0 + (size_t)g * 32 * LL + rc * KC);
            rl[2 * g]     = __ldcs(pa);
            rl[2 * g + 1] = __ldcs(pa + 1);
        }
    };
    auto cp_b = [&](int vch, int stage) {
        const int rc = mapc(vch);
        const uint32_t dst = sbase + (uint32_t)SM_B(stage);
        #pragma unroll
        for (int j = 0; j < 3; j++)
            if (brow_[j] < 88)   // rows 88-95 only feed discarded outputs (n>=88)
                CP_ASYNC_CG(dst + bSts[j], gB + (size_t)brow_[j] * LL + rc * KC + seg * 8);
    };
    auto compute = [&](int stage) {
        const uint32_t saA = sbase + (uint32_t)SM_A(stage);
        const uint32_t saB = sbase + (uint32_t)SM_B(stage);
        #pragma unroll
        for (int ks = 0; ks < 2; ks++) {
            const uint32_t kb = (uint32_t)(kg * 64 + ks * 32);   // this warp's k-half
            uint32_t afr[2][4];
            #pragma unroll
            for (int mi = 0; mi < 2; mi++)
                ldmx4(afr[mi], saA + aBase[mi] + kb);
            uint32_t bfr[2][4];
            #pragma unroll
            for (int j2 = 0; j2 < 2; j2++)
                ldmx4(bfr[j2], saB + bBase[j2] + kb);
            uint32_t bfr2[4];
            if (nfull) ldmx4(bfr2, saB + bBase4_t2 + kb);      // full third tile
            else       ldmx2(bfr2, saB + bBase2_t2 + kb);      // n80-87 only
            #pragma unroll
            for (int mi = 0; mi < 2; mi++) {
                #pragma unroll
                for (int j2 = 0; j2 < 2; j2++) {
                    mma16816(acc[mi][2 * j2],     afr[mi], bfr[j2][0], bfr[j2][1]);
                    mma16816(acc[mi][2 * j2 + 1], afr[mi], bfr[j2][2], bfr[j2][3]);
                }
                mma16816(acc[mi][4], afr[mi], bfr2[0], bfr2[1]);
                if (nfull)
                    mma16816(acc[mi][5], afr[mi], bfr2[2], bfr2[3]);
            }
        }
    };

    float4 ra[4];   // single A register buffer

    // ---- prologue: B(0),B(1) async; A(0) staged; ra <- A(1) ----
    cp_b(0, 0);
    CP_COMMIT();
    cp_b(1, 1);
    CP_COMMIT();
    ldg_a(0, ra);
    sts_count(ra, sbase + (uint32_t)SM_A(0));
    ldg_a(1, ra);                              // ra now holds A(1)

    // ---- main loop: one __syncthreads per chunk; 4-stage rotation,
    //      STS A at distance 1, cp.async B at distance 2, LDG A at distance 2 ----
#define STEP(I, CS, S1, S2)                                          \
    do {                                                             \
        if ((I) + 1 < NCHUNKS)                                       \
            sts_count(ra, sbase + (uint32_t)SM_A(S1));               \
        if ((I) + 2 < NCHUNKS) cp_b((I) + 2, (S2));                  \
        CP_COMMIT();                                                 \
        if ((I) + 2 < NCHUNKS) ldg_a((I) + 2, ra);                   \
        CP_WAIT(2);                                                  \
        __syncthreads();                                             \
        compute(CS);                                                 \
    } while (0)

    #pragma unroll 1
    for (int i = 0; i < NCHUNKS; i += 4) {
        STEP(i,     0, 1, 2);
        STEP(i + 1, 1, 2, 3);
        STEP(i + 2, 2, 3, 0);
        STEP(i + 3, 3, 0, 1);
    }
#undef STEP

    // ---- nz: reduce 8 lanes (same row group) per row ----
    __syncthreads();
    #pragma unroll
    for (int g = 0; g < 2; g++) {
        int v = cnt[g];
        v += __shfl_xor_sync(0xFFFFFFFFu, v, 1);
        v += __shfl_xor_sync(0xFFFFFFFFu, v, 2);
        v += __shfl_xor_sync(0xFFFFFFFFu, v, 4);
        if (seg == 0)
            reinterpret_cast<float*>(smem + SM_NZ)[r0 + 32 * g] = (float)v;
    }

    // ---- cross-k reduction: kg=1 warps dump acc, kg=0 warps sum ----
    float* red = reinterpret_cast<float*>(smem + SM_RED);
    if (kg == 1) {
        const int slot = wid - 4;              // 0..3
        #pragma unroll
        for (int mi = 0; mi < 2; mi++)
            #pragma unroll
            for (int nj = 0; nj < 6; nj++)
                #pragma unroll
                for (int r = 0; r < 4; r++) {
                    int f = mi * 24 + nj * 4 + r;
                    red[f * 128 + slot * 32 + lane] = acc[mi][nj][r];
                }
    }
    __syncthreads();

    if (kg == 0) {
        const int slot = wid;                  // partner is wid+4, same slot index
        #pragma unroll
        for (int mi = 0; mi < 2; mi++)
            #pragma unroll
            for (int nj = 0; nj < 6; nj++)
                #pragma unroll
                for (int r = 0; r < 4; r++) {
                    int f = mi * 24 + nj * 4 + r;
                    acc[mi][nj][r] += red[f * 128 + slot * 32 + lane];
                }

        // ---- epilogue: scale by 1/nz, fold, corr*x + x, leaky relu ----
        const float* snz = reinterpret_cast<const float*>(smem + SM_NZ);
        #pragma unroll
        for (int mi = 0; mi < 2; mi++) {
            #pragma unroll
            for (int hr = 0; hr < 2; hr++) {
                const int m = mbase + 16 * mi + (lane >> 2) + 8 * hr;
                const float inv = 1.0f / (snz[m] + 1e-5f);
                const int l  = mb * TM + m;
                const int bi = l / NW, bj = l % NW;
                const size_t base = (size_t)c * XCH + (size_t)(bi * 9) * WPITCH + (size_t)(bj * 9);
                const float* xp = x + base;
                float* op = out + base;
                #pragma unroll
                for (int nj = 0; nj < 6; nj++) {
                    #pragma unroll
                    for (int e2 = 0; e2 < 2; e2++) {
                        const int n = nbase + 8 * nj + 2 * (lane & 3) + e2;
                        if (n < 81) {
                            const int ki = n / 9, kj = n % 9;
                            const float a  = acc[mi][nj][hr * 2 + e2] * inv;
                            const float xv = xp[ki * WPITCH + kj];
                            const float o  = fmaf(a, xv, xv);
                            op[ki * WPITCH + kj] = (o >= 0.0f) ? o : 0.2f * o;
                        }
                    }
                }
            }
        }
    }
}

// ---------------- launch ----------------
extern "C" void kernel_launch(void* const* d_in, const int* in_sizes, int n_in,
                              void* d_out, int out_size) {
    const float* x;
    const float* attn;
    if (in_sizes[0] == 1492992) {           // x is 1*4*72*72*72
        x = (const float*)d_in[0];
        attn = (const float*)d_in[1];
    } else {
        x = (const float*)d_in[1];
        attn = (const float*)d_in[0];
    }
    cudaFuncSetAttribute(cross_head_main,
                         cudaFuncAttributeMaxDynamicSharedMemorySize, SMEM_BYTES);
    build_b_kernel<<<6912, 256>>>(x);       // 6912*256 == 4*96*4608
    cross_head_main<<<NCH * NBLK_M, 256, SMEM_BYTES>>>(attn, x, (float*)d_out);
}

// round 12
// speedup vs baseline: 1.0255x; 1.0255x over previous
#include <cuda_runtime.h>
#include <cuda_bf16.h>
#include <cstdint>

// ---------------- problem constants ----------------
#define NCH      4
#define LL       4608          // L = nH*nW
#define NW       576           // nW
#define TM       64            // M tile (attn rows per CTA)
#define KC       64            // bf16 K elements per pipeline chunk
#define NCHUNKS  72            // 4608 / 64
#define BNROWS   96            // N padded (81 -> 96)
#define WPITCH   5184          // 72*72
#define XCH      373248        // 72*5184 elements per channel
#define NBLK_M   72            // 4608/64
#define PITCH    144           // padded row pitch (bytes): conflict-free, no swizzle

// ---------------- smem layout (bytes), 3-stage ----------------
#define SM_NZ       0
#define SM_A(s)     (512   + (s)*9216)      // 64 rows x 144B, 3 stages
#define SM_B(s)     (28160 + (s)*13824)     // 96 rows x 144B, 3 stages
#define SM_RED      512                     // 2 x 12288B acc exchange (reuses A stages)
#define SMEM_BYTES  69632

// ---------------- scratch: patches bf16, K-major, padded to 96 rows ----------------
__device__ __nv_bfloat16 g_Bmat[(size_t)NCH * BNROWS * LL];

__device__ __forceinline__ uint32_t smem_to_u32(const void* p) {
    uint32_t a;
    asm("{ .reg .u64 t; cvta.to.shared.u64 t, %1; cvt.u32.u64 %0, t; }" : "=r"(a) : "l"(p));
    return a;
}

__device__ __forceinline__ void ldmx4(uint32_t* r, uint32_t addr) {
    asm volatile("ldmatrix.sync.aligned.m8n8.x4.shared.b16 {%0,%1,%2,%3}, [%4];"
                 : "=r"(r[0]), "=r"(r[1]), "=r"(r[2]), "=r"(r[3]) : "r"(addr));
}
__device__ __forceinline__ void ldmx2(uint32_t* r, uint32_t addr) {
    asm volatile("ldmatrix.sync.aligned.m8n8.x2.shared.b16 {%0,%1}, [%2];"
                 : "=r"(r[0]), "=r"(r[1]) : "r"(addr));
}

__device__ __forceinline__ void mma16816(float* d, const uint32_t* a,
                                         uint32_t b0, uint32_t b1) {
    asm volatile(
        "mma.sync.aligned.m16n8k16.row.col.f32.bf16.bf16.f32 "
        "{%0,%1,%2,%3}, {%4,%5,%6,%7}, {%8,%9}, {%0,%1,%2,%3};"
        : "+f"(d[0]), "+f"(d[1]), "+f"(d[2]), "+f"(d[3])
        : "r"(a[0]), "r"(a[1]), "r"(a[2]), "r"(a[3]), "r"(b0), "r"(b1));
}

#define CP_ASYNC_CG(dst, src) \
    asm volatile("cp.async.cg.shared.global [%0], [%1], 16;" :: "r"(dst), "l"(src))
#define CP_COMMIT() asm volatile("cp.async.commit_group;" ::: "memory")
#define CP_WAIT(n)  asm volatile("cp.async.wait_group %0;" :: "n"(n) : "memory")

// ---------------- prep kernel: fold x -> bf16 patches (K-major, 96 rows) ----------------
__global__ void build_b_kernel(const float* __restrict__ x) {
    int idx = blockIdx.x * blockDim.x + threadIdx.x;  // 6912*256 = 4*96*4608
    int m = idx % LL;
    int k = (idx / LL) % BNROWS;
    int c = idx / (LL * BNROWS);
    float v = 0.0f;
    if (k < 81) {
        int bi = m / NW, bj = m % NW;
        int ki = k / 9,  kj = k % 9;
        v = x[(size_t)c * XCH + (size_t)(bi * 9 + ki) * WPITCH + (bj * 9 + kj)];
    }
    g_Bmat[idx] = __float2bfloat16(v);
}

// ---------------- main fused kernel ----------------
__global__ void __launch_bounds__(256, 2) cross_head_main(
    const float* __restrict__ attn,
    const float* __restrict__ x,
    float* __restrict__ out)
{
    extern __shared__ char smem[];
    const uint32_t sbase = smem_to_u32(smem);
    const int tid  = threadIdx.x;
    const int wid  = tid >> 5;
    const int lane = tid & 31;
    const int c    = blockIdx.x / NBLK_M;
    const int mb   = blockIdx.x % NBLK_M;

    // warp tile: 2m x 2n x 2k split; each warp m32 x n48 x half the k-steps
    const int kg    = wid >> 2;                // k-group 0/1
    const int mbase = ((wid >> 1) & 1) * 32;
    const int nbase = (wid & 1) * 48;
    const bool nfull = (nbase == 0);           // nbase=48: third tile has only n80 valid

    // ---- producer addressing: thread owns 32B (8 floats) x 2 rows per chunk ----
    const int r0  = tid >> 3;                  // 0..31; rows r0, r0+32
    const int seg = tid & 7;                   // 32B segment within 64-col chunk
    const float* gA0 = attn + ((size_t)c * LL + (size_t)(mb * TM + r0)) * LL + seg * 8;
    const __nv_bfloat16* gB = g_Bmat + (size_t)c * BNROWS * LL;

    // A STS offsets within a stage (pitch-144, conflict-free)
    uint32_t aSts[2];
    #pragma unroll
    for (int g = 0; g < 2; g++)
        aSts[g] = (uint32_t)((r0 + 32 * g) * PITCH + seg * 16);

    // B cp.async indices: 3 x 16B per thread per chunk (96 rows x 8 segs = 768)
    int brow_[3];
    uint32_t bSts[3];
    #pragma unroll
    for (int j = 0; j < 3; j++) {
        int idx = tid + j * 256;               // 0..767
        brow_[j] = idx >> 3;
        bSts[j]  = (uint32_t)(brow_[j] * PITCH + (idx & 7) * 16);
    }

    // ---- ldmatrix lane addressing (pitch-144, no xor) ----
    const int la_row = (lane & 7) + ((lane >> 3) & 1) * 8;
    const int la_col = (lane >> 4) * 16;                       // byte
    uint32_t aBase[2];
    #pragma unroll
    for (int mi = 0; mi < 2; mi++)
        aBase[mi] = (uint32_t)((mbase + 16 * mi + la_row) * PITCH) + (uint32_t)la_col;
    const int lb_n   = (lane & 7) + (lane >> 4) * 8;
    const int lb_col = ((lane >> 3) & 1) * 16;                 // byte
    uint32_t bBase[2];
    #pragma unroll
    for (int j2 = 0; j2 < 2; j2++)
        bBase[j2] = (uint32_t)((nbase + 16 * j2 + lb_n) * PITCH) + (uint32_t)lb_col;
    // third tile: x4 form (full) and x2 form (n-half, lanes 0-15 give addrs)
    const uint32_t bBase4_t2 = (uint32_t)((nbase + 32 + lb_n) * PITCH) + (uint32_t)lb_col;
    const uint32_t bBase2_t2 = (uint32_t)((nbase + 32 + (lane & 7)) * PITCH)
                             + (uint32_t)(((lane >> 3) & 1) * 16);

    // 48 accumulators: [mi][nj(6 n8-tiles)][4]
    float acc[2][6][4];
    #pragma unroll
    for (int mi = 0; mi < 2; mi++)
        #pragma unroll
        for (int nj = 0; nj < 6; nj++)
            #pragma unroll
            for (int r = 0; r < 4; r++) acc[mi][nj][r] = 0.0f;

    int cnt[2] = {0, 0};

    auto sts_count = [&](float4 (&rs)[4], uint32_t saStage) {
        #pragma unroll
        for (int g = 0; g < 2; g++) {
            float4 v0 = rs[2 * g], v1 = rs[2 * g + 1];
            cnt[g] += (v0.x != 0.0f) + (v0.y != 0.0f) + (v0.z != 0.0f) + (v0.w != 0.0f)
                    + (v1.x != 0.0f) + (v1.y != 0.0f) + (v1.z != 0.0f) + (v1.w != 0.0f);
            uint4 p;
            asm("cvt.rn.bf16x2.f32 %0, %1, %2;" : "=r"(p.x) : "f"(v0.y), "f"(v0.x));
            asm("cvt.rn.bf16x2.f32 %0, %1, %2;" : "=r"(p.y) : "f"(v0.w), "f"(v0.z));
            asm("cvt.rn.bf16x2.f32 %0, %1, %2;" : "=r"(p.z) : "f"(v1.y), "f"(v1.x));
            asm("cvt.rn.bf16x2.f32 %0, %1, %2;" : "=r"(p.w) : "f"(v1.w), "f"(v1.z));
            asm volatile("st.shared.v4.b32 [%0], {%1,%2,%3,%4};"
                         :: "r"(saStage + aSts[g]), "r"(p.x), "r"(p.y), "r"(p.z), "r"(p.w));
        }
    };
    auto ldg_a = [&](int chunk, float4 (&rl)[4]) {
        #pragma unroll
        for (int g = 0; g < 2; g++) {
            const float4* pa = reinterpret_cast<const float4*>(
                gA0 + (size_t)g * 32 * LL + chunk * KC);
            rl[2 * g]     = __ldcs(pa);
            rl[2 * g + 1] = __ldcs(pa + 1);
        }
    };
    auto cp_b = [&](int chunk, int stage) {
        const uint32_t dst = sbase + (uint32_t)SM_B(stage);
        #pragma unroll
        for (int j = 0; j < 3; j++)
            if (brow_[j] < 88)   // rows 88-95 only feed discarded outputs (n>=88)
                CP_ASYNC_CG(dst + bSts[j], gB + (size_t)brow_[j] * LL + chunk * KC + seg * 8);
    };
    auto compute = [&](int stage) {
        const uint32_t saA = sbase + (uint32_t)SM_A(stage);
        const uint32_t saB = sbase + (uint32_t)SM_B(stage);
        #pragma unroll
        for (int ks = 0; ks < 2; ks++) {
            const uint32_t kb = (uint32_t)(kg * 64 + ks * 32);   // this warp's k-half
            uint32_t afr[2][4];
            #pragma unroll
            for (int mi = 0; mi < 2; mi++)
                ldmx4(afr[mi], saA + aBase[mi] + kb);
            uint32_t bfr[2][4];
            #pragma unroll
            for (int j2 = 0; j2 < 2; j2++)
                ldmx4(bfr[j2], saB + bBase[j2] + kb);
            uint32_t bfr2[4];
            if (nfull) ldmx4(bfr2, saB + bBase4_t2 + kb);      // full third tile
            else       ldmx2(bfr2, saB + bBase2_t2 + kb);      // n80-87 only
            #pragma unroll
            for (int mi = 0; mi < 2; mi++) {
                #pragma unroll
                for (int j2 = 0; j2 < 2; j2++) {
                    mma16816(acc[mi][2 * j2],     afr[mi], bfr[j2][0], bfr[j2][1]);
                    mma16816(acc[mi][2 * j2 + 1], afr[mi], bfr[j2][2], bfr[j2][3]);
                }
                mma16816(acc[mi][4], afr[mi], bfr2[0], bfr2[1]);
                if (nfull)
                    mma16816(acc[mi][5], afr[mi], bfr2[2], bfr2[3]);
            }
        }
    };

    float4 ra[4];   // single A register buffer

    // ---- prologue ----
    cp_b(0, 0);
    CP_COMMIT();
    ldg_a(0, ra);
    sts_count(ra, sbase + (uint32_t)SM_A(0));
    ldg_a(1, ra);                              // ra now holds A(1)

    // ---- main loop: one __syncthreads per chunk; manual 3-unroll, static stages ----
#define STEP(I, CS, NS)                                              \
    do {                                                             \
        if ((I) + 1 < NCHUNKS) {                                     \
            sts_count(ra, sbase + (uint32_t)SM_A(NS));               \
            cp_b((I) + 1, (NS));                                     \
        }                                                            \
        CP_COMMIT();                                                 \
        if ((I) + 2 < NCHUNKS) ldg_a((I) + 2, ra);                   \
        CP_WAIT(1);                                                  \
        __syncthreads();                                             \
        compute(CS);                                                 \
    } while (0)

    #pragma unroll 1
    for (int i = 0; i < NCHUNKS; i += 3) {
        STEP(i,     0, 1);
        STEP(i + 1, 1, 2);
        STEP(i + 2, 2, 0);
    }
#undef STEP

    // ---- nz: reduce 8 lanes (same row group) per row ----
    __syncthreads();
    #pragma unroll
    for (int g = 0; g < 2; g++) {
        int v = cnt[g];
        v += __shfl_xor_sync(0xFFFFFFFFu, v, 1);
        v += __shfl_xor_sync(0xFFFFFFFFu, v, 2);
        v += __shfl_xor_sync(0xFFFFFFFFu, v, 4);
        if (seg == 0)
            reinterpret_cast<float*>(smem + SM_NZ)[r0 + 32 * g] = (float)v;
    }

    // ---- cross-k exchange, both directions (each side dumps the half it won't keep):
    //      kg=1 dumps its mi=0 accs; kg=0 dumps its mi=1 accs. After the barrier,
    //      kg=0 warps own mi=0 rows, kg=1 warps own mi=1 rows. ----
    float* redA = reinterpret_cast<float*>(smem + SM_RED);            // kg1's mi0 (12288B)
    float* redB = reinterpret_cast<float*>(smem + SM_RED + 12288);    // kg0's mi1 (12288B)
    {
        const int slot = wid & 3;
        if (kg == 1) {
            #pragma unroll
            for (int nj = 0; nj < 6; nj++)
                #pragma unroll
                for (int r = 0; r < 4; r++)
                    redA[(nj * 4 + r) * 128 + slot * 32 + lane] = acc[0][nj][r];
        } else {
            #pragma unroll
            for (int nj = 0; nj < 6; nj++)
                #pragma unroll
                for (int r = 0; r < 4; r++)
                    redB[(nj * 4 + r) * 128 + slot * 32 + lane] = acc[1][nj][r];
        }
    }
    __syncthreads();

    // ---- sum partner half + epilogue, one mi-half per warp ----
    {
        const int slot = wid & 3;
        const float* snz = reinterpret_cast<const float*>(smem + SM_NZ);

        auto epi = [&](float (&a)[6][4], const float* rsrc, int mi) {
            #pragma unroll
            for (int nj = 0; nj < 6; nj++)
                #pragma unroll
                for (int r = 0; r < 4; r++)
                    a[nj][r] += rsrc[(nj * 4 + r) * 128 + slot * 32 + lane];

            #pragma unroll
            for (int hr = 0; hr < 2; hr++) {
                const int m = mbase + 16 * mi + (lane >> 2) + 8 * hr;
                const float inv = 1.0f / (snz[m] + 1e-5f);
                const int l  = mb * TM + m;
                const int bi = l / NW, bj = l % NW;
                const size_t base = (size_t)c * XCH + (size_t)(bi * 9) * WPITCH + (size_t)(bj * 9);
                const float* xp = x + base;
                float* op = out + base;
                #pragma unroll
                for (int nj = 0; nj < 6; nj++) {
                    #pragma unroll
                    for (int e2 = 0; e2 < 2; e2++) {
                        const int n = nbase + 8 * nj + 2 * (lane & 3) + e2;
                        if (n < 81) {
                            const int ki = n / 9, kj = n % 9;
                            const float a2 = a[nj][hr * 2 + e2] * inv;
                            const float xv = xp[ki * WPITCH + kj];
                            const float o  = fmaf(a2, xv, xv);
                            op[ki * WPITCH + kj] = (o >= 0.0f) ? o : 0.2f * o;
                        }
                    }
                }
            }
        };

        if (kg == 0) epi(acc[0], redA, 0);
        else         epi(acc[1], redB, 1);
    }
}

// ---------------- launch ----------------
extern "C" void kernel_launch(void* const* d_in, const int* in_sizes, int n_in,
                              void* d_out, int out_size) {
    const float* x;
    const float* attn;
    if (in_sizes[0] == 1492992) {           // x is 1*4*72*72*72
        x = (const float*)d_in[0];
        attn = (const float*)d_in[1];
    } else {
        x = (const float*)d_in[1];
        attn = (const float*)d_in[0];
    }
    cudaFuncSetAttribute(cross_head_main,
                         cudaFuncAttributeMaxDynamicSharedMemorySize, SMEM_BYTES);
    build_b_kernel<<<6912, 256>>>(x);       // 6912*256 == 4*96*4608
    cross_head_main<<<NCH * NBLK_M, 256, SMEM_BYTES>>>(attn, x, (float*)d_out);
}

// round 13
// speedup vs baseline: 1.0579x; 1.0316x over previous
#include <cuda_runtime.h>
#include <cuda_bf16.h>
#include <cstdint>

// ---------------- problem constants ----------------
#define NCH      4
#define LL       4608          // L = nH*nW
#define NW       576           // nW
#define TM       64            // M tile (attn rows per CTA)
#define KC       64            // bf16 K elements per pipeline chunk
#define NCHUNKS  72            // 4608 / 64
#define BNROWS   96            // N padded (81 -> 96)
#define WPITCH   5184          // 72*72
#define XCH      373248        // 72*5184 elements per channel
#define NBLK_M   72            // 4608/64
#define PITCH    144           // padded row pitch (bytes): conflict-free, no swizzle

// ---------------- smem layout (bytes), 3-stage ----------------
#define SM_NZ       0
#define SM_A(s)     (512   + (s)*9216)      // 64 rows x 144B, 3 stages
#define SM_B(s)     (28160 + (s)*13824)     // 96 rows x 144B, 3 stages
#define SM_RED      512                     // 2 x 12288B acc exchange (reuses A stages)
#define SMEM_BYTES  69632

// ---------------- scratch: patches bf16, K-major, padded to 96 rows ----------------
__device__ __nv_bfloat16 g_Bmat[(size_t)NCH * BNROWS * LL];

__device__ __forceinline__ uint32_t smem_to_u32(const void* p) {
    uint32_t a;
    asm("{ .reg .u64 t; cvta.to.shared.u64 t, %1; cvt.u32.u64 %0, t; }" : "=r"(a) : "l"(p));
    return a;
}

__device__ __forceinline__ void ldmx4(uint32_t* r, uint32_t addr) {
    asm volatile("ldmatrix.sync.aligned.m8n8.x4.shared.b16 {%0,%1,%2,%3}, [%4];"
                 : "=r"(r[0]), "=r"(r[1]), "=r"(r[2]), "=r"(r[3]) : "r"(addr));
}
__device__ __forceinline__ void ldmx2(uint32_t* r, uint32_t addr) {
    asm volatile("ldmatrix.sync.aligned.m8n8.x2.shared.b16 {%0,%1}, [%2];"
                 : "=r"(r[0]), "=r"(r[1]) : "r"(addr));
}

__device__ __forceinline__ void mma16816(float* d, const uint32_t* a,
                                         uint32_t b0, uint32_t b1) {
    asm volatile(
        "mma.sync.aligned.m16n8k16.row.col.f32.bf16.bf16.f32 "
        "{%0,%1,%2,%3}, {%4,%5,%6,%7}, {%8,%9}, {%0,%1,%2,%3};"
        : "+f"(d[0]), "+f"(d[1]), "+f"(d[2]), "+f"(d[3])
        : "r"(a[0]), "r"(a[1]), "r"(a[2]), "r"(a[3]), "r"(b0), "r"(b1));
}

#define CP_ASYNC_CG(dst, src) \
    asm volatile("cp.async.cg.shared.global [%0], [%1], 16;" :: "r"(dst), "l"(src))
#define CP_COMMIT() asm volatile("cp.async.commit_group;" ::: "memory")
#define CP_WAIT(n)  asm volatile("cp.async.wait_group %0;" :: "n"(n) : "memory")

// ---------------- prep kernel v2: coalesced tiled fold x -> bf16 patches ----------------
// 256 blocks: c(4) x bi(8) x bjg(8). Each block: read 9 x 648 fp32 slab coalesced,
// emit 88 B-rows (81 data + 7 zero-pad) x 72 m as packed bf16x2. Rows 88-95 of
// g_Bmat are never read by the main kernel (cp_b skips brow>=88) and stay untouched.
__global__ void __launch_bounds__(256) build_b_kernel(const float* __restrict__ x) {
    __shared__ float sx[9][648];
    const int bx  = blockIdx.x;
    const int c   = bx >> 6;
    const int bi  = (bx >> 3) & 7;
    const int bjg = bx & 7;
    const int t   = threadIdx.x;

    // read phase: 1458 float4 loads, fully coalesced
    const float* src = x + (size_t)c * XCH + (size_t)(bi * 9) * WPITCH + bjg * 648;
    #pragma unroll
    for (int i = 0; i < 6; i++) {
        int v = t + i * 256;
        if (v < 1458) {
            int row = v / 162, col = v % 162;
            float4 d = *reinterpret_cast<const float4*>(src + (size_t)row * WPITCH + col * 4);
            *reinterpret_cast<float4*>(&sx[row][col * 4]) = d;
        }
    }
    __syncthreads();

    // write phase: 88 rows x 36 bf16x2 slots = 3168
    const int m0 = bi * 576 + bjg * 72;
    uint32_t* dst32 = reinterpret_cast<uint32_t*>(g_Bmat);
    #pragma unroll
    for (int i = 0; i < 13; i++) {
        int s = t + i * 256;
        if (s < 3168) {
            int r = s / 36, p = s % 36;
            uint32_t pk = 0;
            if (r < 81) {
                int ki = r / 9, kj = r % 9;
                float v0 = sx[ki][18 * p + kj];
                float v1 = sx[ki][18 * p + 9 + kj];
                asm("cvt.rn.bf16x2.f32 %0, %1, %2;" : "=r"(pk) : "f"(v1), "f"(v0));
            }
            dst32[(((size_t)(c * BNROWS + r)) * LL + m0) / 2 + p] = pk;
        }
    }
}

// ---------------- main fused kernel ----------------
__global__ void __launch_bounds__(256, 2) cross_head_main(
    const float* __restrict__ attn,
    const float* __restrict__ x,
    float* __restrict__ out)
{
    extern __shared__ char smem[];
    const uint32_t sbase = smem_to_u32(smem);
    const int tid  = threadIdx.x;
    const int wid  = tid >> 5;
    const int lane = tid & 31;
    const int c    = blockIdx.x / NBLK_M;
    const int mb   = blockIdx.x % NBLK_M;

    // warp tile: 2m x 2n x 2k split; each warp m32 x n48 x half the k-steps
    const int kg    = wid >> 2;                // k-group 0/1
    const int mbase = ((wid >> 1) & 1) * 32;
    const int nbase = (wid & 1) * 48;
    const bool nfull = (nbase == 0);           // nbase=48: third tile has only n80 valid

    // ---- producer addressing: thread owns 32B (8 floats) x 2 rows per chunk ----
    const int r0  = tid >> 3;                  // 0..31; rows r0, r0+32
    const int seg = tid & 7;                   // 32B segment within 64-col chunk
    const float* gA0 = attn + ((size_t)c * LL + (size_t)(mb * TM + r0)) * LL + seg * 8;
    const __nv_bfloat16* gB = g_Bmat + (size_t)c * BNROWS * LL;

    // A STS offsets within a stage (pitch-144, conflict-free)
    uint32_t aSts[2];
    #pragma unroll
    for (int g = 0; g < 2; g++)
        aSts[g] = (uint32_t)((r0 + 32 * g) * PITCH + seg * 16);

    // B cp.async indices: 3 x 16B per thread per chunk (96 rows x 8 segs = 768)
    int brow_[3];
    uint32_t bSts[3];
    #pragma unroll
    for (int j = 0; j < 3; j++) {
        int idx = tid + j * 256;               // 0..767
        brow_[j] = idx >> 3;
        bSts[j]  = (uint32_t)(brow_[j] * PITCH + (idx & 7) * 16);
    }

    // ---- ldmatrix lane addressing (pitch-144, no xor) ----
    const int la_row = (lane & 7) + ((lane >> 3) & 1) * 8;
    const int la_col = (lane >> 4) * 16;                       // byte
    uint32_t aBase[2];
    #pragma unroll
    for (int mi = 0; mi < 2; mi++)
        aBase[mi] = (uint32_t)((mbase + 16 * mi + la_row) * PITCH) + (uint32_t)la_col;
    const int lb_n   = (lane & 7) + (lane >> 4) * 8;
    const int lb_col = ((lane >> 3) & 1) * 16;                 // byte
    uint32_t bBase[2];
    #pragma unroll
    for (int j2 = 0; j2 < 2; j2++)
        bBase[j2] = (uint32_t)((nbase + 16 * j2 + lb_n) * PITCH) + (uint32_t)lb_col;
    // third tile: x4 form (full) and x2 form (n-half, lanes 0-15 give addrs)
    const uint32_t bBase4_t2 = (uint32_t)((nbase + 32 + lb_n) * PITCH) + (uint32_t)lb_col;
    const uint32_t bBase2_t2 = (uint32_t)((nbase + 32 + (lane & 7)) * PITCH)
                             + (uint32_t)(((lane >> 3) & 1) * 16);

    // 48 accumulators: [mi][nj(6 n8-tiles)][4]
    float acc[2][6][4];
    #pragma unroll
    for (int mi = 0; mi < 2; mi++)
        #pragma unroll
        for (int nj = 0; nj < 6; nj++)
            #pragma unroll
            for (int r = 0; r < 4; r++) acc[mi][nj][r] = 0.0f;

    int cnt[2] = {0, 0};

    auto sts_count = [&](float4 (&rs)[4], uint32_t saStage) {
        #pragma unroll
        for (int g = 0; g < 2; g++) {
            float4 v0 = rs[2 * g], v1 = rs[2 * g + 1];
            cnt[g] += (v0.x != 0.0f) + (v0.y != 0.0f) + (v0.z != 0.0f) + (v0.w != 0.0f)
                    + (v1.x != 0.0f) + (v1.y != 0.0f) + (v1.z != 0.0f) + (v1.w != 0.0f);
            uint4 p;
            asm("cvt.rn.bf16x2.f32 %0, %1, %2;" : "=r"(p.x) : "f"(v0.y), "f"(v0.x));
            asm("cvt.rn.bf16x2.f32 %0, %1, %2;" : "=r"(p.y) : "f"(v0.w), "f"(v0.z));
            asm("cvt.rn.bf16x2.f32 %0, %1, %2;" : "=r"(p.z) : "f"(v1.y), "f"(v1.x));
            asm("cvt.rn.bf16x2.f32 %0, %1, %2;" : "=r"(p.w) : "f"(v1.w), "f"(v1.z));
            asm volatile("st.shared.v4.b32 [%0], {%1,%2,%3,%4};"
                         :: "r"(saStage + aSts[g]), "r"(p.x), "r"(p.y), "r"(p.z), "r"(p.w));
        }
    };
    auto ldg_a = [&](int chunk, float4 (&rl)[4]) {
        #pragma unroll
        for (int g = 0; g < 2; g++) {
            const float4* pa = reinterpret_cast<const float4*>(
                gA0 + (size_t)g * 32 * LL + chunk * KC);
            rl[2 * g]     = __ldcs(pa);
            rl[2 * g + 1] = __ldcs(pa + 1);
        }
    };
    auto cp_b = [&](int chunk, int stage) {
        const uint32_t dst = sbase + (uint32_t)SM_B(stage);
        #pragma unroll
        for (int j = 0; j < 3; j++)
            if (brow_[j] < 88)   // rows 88-95 only feed discarded outputs (n>=88)
                CP_ASYNC_CG(dst + bSts[j], gB + (size_t)brow_[j] * LL + chunk * KC + seg * 8);
    };
    auto compute = [&](int stage) {
        const uint32_t saA = sbase + (uint32_t)SM_A(stage);
        const uint32_t saB = sbase + (uint32_t)SM_B(stage);
        #pragma unroll
        for (int ks = 0; ks < 2; ks++) {
            const uint32_t kb = (uint32_t)(kg * 64 + ks * 32);   // this warp's k-half
            uint32_t afr[2][4];
            #pragma unroll
            for (int mi = 0; mi < 2; mi++)
                ldmx4(afr[mi], saA + aBase[mi] + kb);
            uint32_t bfr[2][4];
            #pragma unroll
            for (int j2 = 0; j2 < 2; j2++)
                ldmx4(bfr[j2], saB + bBase[j2] + kb);
            uint32_t bfr2[4];
            if (nfull) ldmx4(bfr2, saB + bBase4_t2 + kb);      // full third tile
            else       ldmx2(bfr2, saB + bBase2_t2 + kb);      // n80-87 only
            #pragma unroll
            for (int mi = 0; mi < 2; mi++) {
                #pragma unroll
                for (int j2 = 0; j2 < 2; j2++) {
                    mma16816(acc[mi][2 * j2],     afr[mi], bfr[j2][0], bfr[j2][1]);
                    mma16816(acc[mi][2 * j2 + 1], afr[mi], bfr[j2][2], bfr[j2][3]);
                }
                mma16816(acc[mi][4], afr[mi], bfr2[0], bfr2[1]);
                if (nfull)
                    mma16816(acc[mi][5], afr[mi], bfr2[2], bfr2[3]);
            }
        }
    };

    float4 ra[4];   // single A register buffer

    // ---- prologue ----
    cp_b(0, 0);
    CP_COMMIT();
    ldg_a(0, ra);
    sts_count(ra, sbase + (uint32_t)SM_A(0));
    ldg_a(1, ra);                              // ra now holds A(1)

    // ---- main loop: one __syncthreads per chunk; manual 3-unroll, static stages.
    //      cp.async issued before STS so it isn't queued behind ra's scoreboard. ----
#define STEP(I, CS, NS)                                              \
    do {                                                             \
        if ((I) + 1 < NCHUNKS) {                                     \
            cp_b((I) + 1, (NS));                                     \
            sts_count(ra, sbase + (uint32_t)SM_A(NS));               \
        }                                                            \
        CP_COMMIT();                                                 \
        if ((I) + 2 < NCHUNKS) ldg_a((I) + 2, ra);                   \
        CP_WAIT(1);                                                  \
        __syncthreads();                                             \
        compute(CS);                                                 \
    } while (0)

    #pragma unroll 1
    for (int i = 0; i < NCHUNKS; i += 3) {
        STEP(i,     0, 1);
        STEP(i + 1, 1, 2);
        STEP(i + 2, 2, 0);
    }
#undef STEP

    // ---- nz: reduce 8 lanes (same row group) per row ----
    __syncthreads();
    #pragma unroll
    for (int g = 0; g < 2; g++) {
        int v = cnt[g];
        v += __shfl_xor_sync(0xFFFFFFFFu, v, 1);
        v += __shfl_xor_sync(0xFFFFFFFFu, v, 2);
        v += __shfl_xor_sync(0xFFFFFFFFu, v, 4);
        if (seg == 0)
            reinterpret_cast<float*>(smem + SM_NZ)[r0 + 32 * g] = (float)v;
    }

    // ---- cross-k exchange, both directions (each side dumps the half it won't keep):
    //      kg=1 dumps its mi=0 accs; kg=0 dumps its mi=1 accs. ----
    float* redA = reinterpret_cast<float*>(smem + SM_RED);            // kg1's mi0
    float* redB = reinterpret_cast<float*>(smem + SM_RED + 12288);    // kg0's mi1
    {
        const int slot = wid & 3;
        if (kg == 1) {
            #pragma unroll
            for (int nj = 0; nj < 6; nj++)
                #pragma unroll
                for (int r = 0; r < 4; r++)
                    redA[(nj * 4 + r) * 128 + slot * 32 + lane] = acc[0][nj][r];
        } else {
            #pragma unroll
            for (int nj = 0; nj < 6; nj++)
                #pragma unroll
                for (int r = 0; r < 4; r++)
                    redB[(nj * 4 + r) * 128 + slot * 32 + lane] = acc[1][nj][r];
        }
    }
    __syncthreads();

    // ---- sum partner half + epilogue, one mi-half per warp ----
    {
        const int slot = wid & 3;
        const float* snz = reinterpret_cast<const float*>(smem + SM_NZ);

        auto epi = [&](float (&a)[6][4], const float* rsrc, int mi) {
            #pragma unroll
            for (int nj = 0; nj < 6; nj++)
                #pragma unroll
                for (int r = 0; r < 4; r++)
                    a[nj][r] += rsrc[(nj * 4 + r) * 128 + slot * 32 + lane];

            #pragma unroll
            for (int hr = 0; hr < 2; hr++) {
                const int m = mbase + 16 * mi + (lane >> 2) + 8 * hr;
                const float inv = 1.0f / (snz[m] + 1e-5f);
                const int l  = mb * TM + m;
                const int bi = l / NW, bj = l % NW;
                const size_t base = (size_t)c * XCH + (size_t)(bi * 9) * WPITCH + (size_t)(bj * 9);
                const float* xp = x + base;
                float* op = out + base;
                #pragma unroll
                for (int nj = 0; nj < 6; nj++) {
                    #pragma unroll
                    for (int e2 = 0; e2 < 2; e2++) {
                        const int n = nbase + 8 * nj + 2 * (lane & 3) + e2;
                        if (n < 81) {
                            const int ki = n / 9, kj = n % 9;
                            const float a2 = a[nj][hr * 2 + e2] * inv;
                            const float xv = xp[ki * WPITCH + kj];
                            const float o  = fmaf(a2, xv, xv);
                            op[ki * WPITCH + kj] = (o >= 0.0f) ? o : 0.2f * o;
                        }
                    }
                }
            }
        };

        if (kg == 0) epi(acc[0], redA, 0);
        else         epi(acc[1], redB, 1);
    }
}

// ---------------- launch ----------------
extern "C" void kernel_launch(void* const* d_in, const int* in_sizes, int n_in,
                              void* d_out, int out_size) {
    const float* x;
    const float* attn;
    if (in_sizes[0] == 1492992) {           // x is 1*4*72*72*72
        x = (const float*)d_in[0];
        attn = (const float*)d_in[1];
    } else {
        x = (const float*)d_in[1];
        attn = (const float*)d_in[0];
    }
    cudaFuncSetAttribute(cross_head_main,
                         cudaFuncAttributeMaxDynamicSharedMemorySize, SMEM_BYTES);
    build_b_kernel<<<256, 256>>>(x);
    cross_head_main<<<NCH * NBLK_M, 256, SMEM_BYTES>>>(attn, x, (float*)d_out);
}

// round 14
// speedup vs baseline: 1.0698x; 1.0112x over previous
#include <cuda_runtime.h>
#include <cuda_bf16.h>
#include <cstdint>

// ---------------- problem constants ----------------
#define NCH      4
#define LL       4608          // L = nH*nW
#define NW       576           // nW
#define TM       64            // M tile (attn rows per CTA)
#define KC       64            // bf16 K elements per pipeline chunk
#define NCHUNKS  72            // 4608 / 64
#define BNROWS   96            // N padded (81 -> 96)
#define WPITCH   5184          // 72*72
#define XCH      373248        // 72*5184 elements per channel
#define NBLK_M   72            // 4608/64
#define PITCH    144           // padded row pitch (bytes): conflict-free, no swizzle

// ---------------- smem layout (bytes), 3-stage ----------------
#define SM_NZ       0
#define SM_A(s)     (512   + (s)*9216)      // 64 rows x 144B, 3 stages
#define SM_B(s)     (28160 + (s)*13824)     // 96 rows x 144B, 3 stages
#define SM_RED      512                     // 2 x 12288B acc exchange (reuses A stages)
#define SMEM_BYTES  69632

// ---------------- scratch: patches bf16, K-major, padded to 96 rows ----------------
__device__ __nv_bfloat16 g_Bmat[(size_t)NCH * BNROWS * LL];

__device__ __forceinline__ uint32_t smem_to_u32(const void* p) {
    uint32_t a;
    asm("{ .reg .u64 t; cvta.to.shared.u64 t, %1; cvt.u32.u64 %0, t; }" : "=r"(a) : "l"(p));
    return a;
}

__device__ __forceinline__ void ldmx4(uint32_t* r, uint32_t addr) {
    asm volatile("ldmatrix.sync.aligned.m8n8.x4.shared.b16 {%0,%1,%2,%3}, [%4];"
                 : "=r"(r[0]), "=r"(r[1]), "=r"(r[2]), "=r"(r[3]) : "r"(addr));
}
__device__ __forceinline__ void ldmx2(uint32_t* r, uint32_t addr) {
    asm volatile("ldmatrix.sync.aligned.m8n8.x2.shared.b16 {%0,%1}, [%2];"
                 : "=r"(r[0]), "=r"(r[1]) : "r"(addr));
}

__device__ __forceinline__ void mma16816(float* d, const uint32_t* a,
                                         uint32_t b0, uint32_t b1) {
    asm volatile(
        "mma.sync.aligned.m16n8k16.row.col.f32.bf16.bf16.f32 "
        "{%0,%1,%2,%3}, {%4,%5,%6,%7}, {%8,%9}, {%0,%1,%2,%3};"
        : "+f"(d[0]), "+f"(d[1]), "+f"(d[2]), "+f"(d[3])
        : "r"(a[0]), "r"(a[1]), "r"(a[2]), "r"(a[3]), "r"(b0), "r"(b1));
}

#define CP_ASYNC_CG(dst, src) \
    asm volatile("cp.async.cg.shared.global [%0], [%1], 16;" :: "r"(dst), "l"(src))
#define CP_COMMIT() asm volatile("cp.async.commit_group;" ::: "memory")
#define CP_WAIT(n)  asm volatile("cp.async.wait_group %0;" :: "n"(n) : "memory")

// ---------------- prep kernel v3: coalesced tiled fold, 512 fine-grain blocks ----------
// 512 blocks: c(4) x bi(8) x bjg(16). Each block: read a 9 x 324 fp32 slab coalesced,
// emit 88 B-rows (81 data + 7 zero-pad) x 36 m as packed bf16x2. Rows 88-95 of
// g_Bmat are never read by the main kernel (cp_b skips brow>=88) and stay untouched.
__global__ void __launch_bounds__(256) build_b_kernel(const float* __restrict__ x) {
    __shared__ float sx[9][324];
    const int bx  = blockIdx.x;
    const int c   = bx >> 7;
    const int bi  = (bx >> 4) & 7;
    const int bjg = bx & 15;
    const int t   = threadIdx.x;

    // read phase: 729 float4 loads, fully coalesced
    const float* src = x + (size_t)c * XCH + (size_t)(bi * 9) * WPITCH + bjg * 324;
    #pragma unroll
    for (int i = 0; i < 3; i++) {
        int v = t + i * 256;
        if (v < 729) {
            int row = v / 81, col = v % 81;
            float4 d = *reinterpret_cast<const float4*>(src + (size_t)row * WPITCH + col * 4);
            *reinterpret_cast<float4*>(&sx[row][col * 4]) = d;
        }
    }
    __syncthreads();

    // write phase: 88 rows x 18 bf16x2 slots = 1584
    const int m0 = bi * 576 + bjg * 36;
    uint32_t* dst32 = reinterpret_cast<uint32_t*>(g_Bmat);
    #pragma unroll
    for (int i = 0; i < 7; i++) {
        int s = t + i * 256;
        if (s < 1584) {
            int r = s / 18, p = s % 18;
            uint32_t pk = 0;
            if (r < 81) {
                int ki = r / 9, kj = r % 9;
                float v0 = sx[ki][18 * p + kj];
                float v1 = sx[ki][18 * p + 9 + kj];
                asm("cvt.rn.bf16x2.f32 %0, %1, %2;" : "=r"(pk) : "f"(v1), "f"(v0));
            }
            dst32[(((size_t)(c * BNROWS + r)) * LL + m0) / 2 + p] = pk;
        }
    }
}

// ---------------- main fused kernel ----------------
__global__ void __launch_bounds__(256, 2) cross_head_main(
    const float* __restrict__ attn,
    const float* __restrict__ x,
    float* __restrict__ out)
{
    extern __shared__ char smem[];
    const uint32_t sbase = smem_to_u32(smem);
    const int tid  = threadIdx.x;
    const int wid  = tid >> 5;
    const int lane = tid & 31;
    const int c    = blockIdx.x / NBLK_M;
    const int mb   = blockIdx.x % NBLK_M;

    // warp tile: 2m x 2n x 2k split; each warp m32 x n48 x half the k-steps
    const int kg    = wid >> 2;                // k-group 0/1
    const int mbase = ((wid >> 1) & 1) * 32;
    const int nbase = (wid & 1) * 48;
    const bool nfull = (nbase == 0);           // nbase=48: third tile has only n80 valid

    // ---- producer addressing: thread owns 32B (8 floats) x 2 rows per chunk ----
    const int r0  = tid >> 3;                  // 0..31; rows r0, r0+32
    const int seg = tid & 7;                   // 32B segment within 64-col chunk
    const float* gA0 = attn + ((size_t)c * LL + (size_t)(mb * TM + r0)) * LL + seg * 8;
    const __nv_bfloat16* gB = g_Bmat + (size_t)c * BNROWS * LL;

    // A STS offsets within a stage (pitch-144, conflict-free)
    uint32_t aSts[2];
    #pragma unroll
    for (int g = 0; g < 2; g++)
        aSts[g] = (uint32_t)((r0 + 32 * g) * PITCH + seg * 16);

    // B cp.async indices: 3 x 16B per thread per chunk (96 rows x 8 segs = 768)
    int brow_[3];
    uint32_t bSts[3];
    #pragma unroll
    for (int j = 0; j < 3; j++) {
        int idx = tid + j * 256;               // 0..767
        brow_[j] = idx >> 3;
        bSts[j]  = (uint32_t)(brow_[j] * PITCH + (idx & 7) * 16);
    }

    // ---- ldmatrix lane addressing (pitch-144, no xor) ----
    const int la_row = (lane & 7) + ((lane >> 3) & 1) * 8;
    const int la_col = (lane >> 4) * 16;                       // byte
    uint32_t aBase[2];
    #pragma unroll
    for (int mi = 0; mi < 2; mi++)
        aBase[mi] = (uint32_t)((mbase + 16 * mi + la_row) * PITCH) + (uint32_t)la_col;
    const int lb_n   = (lane & 7) + (lane >> 4) * 8;
    const int lb_col = ((lane >> 3) & 1) * 16;                 // byte
    uint32_t bBase[2];
    #pragma unroll
    for (int j2 = 0; j2 < 2; j2++)
        bBase[j2] = (uint32_t)((nbase + 16 * j2 + lb_n) * PITCH) + (uint32_t)lb_col;
    // third tile: x4 form (full) and x2 form (n-half, lanes 0-15 give addrs)
    const uint32_t bBase4_t2 = (uint32_t)((nbase + 32 + lb_n) * PITCH) + (uint32_t)lb_col;
    const uint32_t bBase2_t2 = (uint32_t)((nbase + 32 + (lane & 7)) * PITCH)
                             + (uint32_t)(((lane >> 3) & 1) * 16);

    // 48 accumulators: [mi][nj(6 n8-tiles)][4]
    float acc[2][6][4];
    #pragma unroll
    for (int mi = 0; mi < 2; mi++)
        #pragma unroll
        for (int nj = 0; nj < 6; nj++)
            #pragma unroll
            for (int r = 0; r < 4; r++) acc[mi][nj][r] = 0.0f;

    int cnt[2] = {0, 0};

    auto sts_count = [&](float4 (&rs)[4], uint32_t saStage) {
        #pragma unroll
        for (int g = 0; g < 2; g++) {
            float4 v0 = rs[2 * g], v1 = rs[2 * g + 1];
            cnt[g] += (v0.x != 0.0f) + (v0.y != 0.0f) + (v0.z != 0.0f) + (v0.w != 0.0f)
                    + (v1.x != 0.0f) + (v1.y != 0.0f) + (v1.z != 0.0f) + (v1.w != 0.0f);
            uint4 p;
            asm("cvt.rn.bf16x2.f32 %0, %1, %2;" : "=r"(p.x) : "f"(v0.y), "f"(v0.x));
            asm("cvt.rn.bf16x2.f32 %0, %1, %2;" : "=r"(p.y) : "f"(v0.w), "f"(v0.z));
            asm("cvt.rn.bf16x2.f32 %0, %1, %2;" : "=r"(p.z) : "f"(v1.y), "f"(v1.x));
            asm("cvt.rn.bf16x2.f32 %0, %1, %2;" : "=r"(p.w) : "f"(v1.w), "f"(v1.z));
            asm volatile("st.shared.v4.b32 [%0], {%1,%2,%3,%4};"
                         :: "r"(saStage + aSts[g]), "r"(p.x), "r"(p.y), "r"(p.z), "r"(p.w));
        }
    };
    auto ldg_a = [&](int chunk, float4 (&rl)[4]) {
        #pragma unroll
        for (int g = 0; g < 2; g++) {
            const float4* pa = reinterpret_cast<const float4*>(
                gA0 + (size_t)g * 32 * LL + chunk * KC);
            rl[2 * g]     = __ldcs(pa);
            rl[2 * g + 1] = __ldcs(pa + 1);
        }
    };
    auto cp_b = [&](int chunk, int stage) {
        const uint32_t dst = sbase + (uint32_t)SM_B(stage);
        #pragma unroll
        for (int j = 0; j < 3; j++)
            if (brow_[j] < 88)   // rows 88-95 only feed discarded outputs (n>=88)
                CP_ASYNC_CG(dst + bSts[j], gB + (size_t)brow_[j] * LL + chunk * KC + seg * 8);
    };
    auto compute = [&](int stage) {
        const uint32_t saA = sbase + (uint32_t)SM_A(stage);
        const uint32_t saB = sbase + (uint32_t)SM_B(stage);
        #pragma unroll
        for (int ks = 0; ks < 2; ks++) {
            const uint32_t kb = (uint32_t)(kg * 64 + ks * 32);   // this warp's k-half
            uint32_t afr[2][4];
            #pragma unroll
            for (int mi = 0; mi < 2; mi++)
                ldmx4(afr[mi], saA + aBase[mi] + kb);
            uint32_t bfr[2][4];
            #pragma unroll
            for (int j2 = 0; j2 < 2; j2++)
                ldmx4(bfr[j2], saB + bBase[j2] + kb);
            uint32_t bfr2[4];
            if (nfull) ldmx4(bfr2, saB + bBase4_t2 + kb);      // full third tile
            else       ldmx2(bfr2, saB + bBase2_t2 + kb);      // n80-87 only
            #pragma unroll
            for (int mi = 0; mi < 2; mi++) {
                #pragma unroll
                for (int j2 = 0; j2 < 2; j2++) {
                    mma16816(acc[mi][2 * j2],     afr[mi], bfr[j2][0], bfr[j2][1]);
                    mma16816(acc[mi][2 * j2 + 1], afr[mi], bfr[j2][2], bfr[j2][3]);
                }
                mma16816(acc[mi][4], afr[mi], bfr2[0], bfr2[1]);
                if (nfull)
                    mma16816(acc[mi][5], afr[mi], bfr2[2], bfr2[3]);
            }
        }
    };

    float4 ra[4];   // single A register buffer

    // ---- prologue ----
    cp_b(0, 0);
    CP_COMMIT();
    ldg_a(0, ra);
    sts_count(ra, sbase + (uint32_t)SM_A(0));
    ldg_a(1, ra);                              // ra now holds A(1)

    // ---- main loop: one __syncthreads per chunk; manual 3-unroll, static stages.
    //      cp.async issued before STS so it isn't queued behind ra's scoreboard. ----
#define STEP(I, CS, NS)                                              \
    do {                                                             \
        if ((I) + 1 < NCHUNKS) {                                     \
            cp_b((I) + 1, (NS));                                     \
            sts_count(ra, sbase + (uint32_t)SM_A(NS));               \
        }                                                            \
        CP_COMMIT();                                                 \
        if ((I) + 2 < NCHUNKS) ldg_a((I) + 2, ra);                   \
        CP_WAIT(1);                                                  \
        __syncthreads();                                             \
        compute(CS);                                                 \
    } while (0)

    #pragma unroll 1
    for (int i = 0; i < NCHUNKS; i += 3) {
        STEP(i,     0, 1);
        STEP(i + 1, 1, 2);
        STEP(i + 2, 2, 0);
    }
#undef STEP

    // ---- nz: reduce 8 lanes (same row group) per row ----
    __syncthreads();
    #pragma unroll
    for (int g = 0; g < 2; g++) {
        int v = cnt[g];
        v += __shfl_xor_sync(0xFFFFFFFFu, v, 1);
        v += __shfl_xor_sync(0xFFFFFFFFu, v, 2);
        v += __shfl_xor_sync(0xFFFFFFFFu, v, 4);
        if (seg == 0)
            reinterpret_cast<float*>(smem + SM_NZ)[r0 + 32 * g] = (float)v;
    }

    // ---- cross-k exchange, both directions (each side dumps the half it won't keep):
    //      kg=1 dumps its mi=0 accs; kg=0 dumps its mi=1 accs. ----
    float* redA = reinterpret_cast<float*>(smem + SM_RED);            // kg1's mi0
    float* redB = reinterpret_cast<float*>(smem + SM_RED + 12288);    // kg0's mi1
    {
        const int slot = wid & 3;
        if (kg == 1) {
            #pragma unroll
            for (int nj = 0; nj < 6; nj++)
                #pragma unroll
                for (int r = 0; r < 4; r++)
                    redA[(nj * 4 + r) * 128 + slot * 32 + lane] = acc[0][nj][r];
        } else {
            #pragma unroll
            for (int nj = 0; nj < 6; nj++)
                #pragma unroll
                for (int r = 0; r < 4; r++)
                    redB[(nj * 4 + r) * 128 + slot * 32 + lane] = acc[1][nj][r];
        }
    }
    __syncthreads();

    // ---- sum partner half + epilogue, one mi-half per warp ----
    {
        const int slot = wid & 3;
        const float* snz = reinterpret_cast<const float*>(smem + SM_NZ);

        auto epi = [&](float (&a)[6][4], const float* rsrc, int mi) {
            #pragma unroll
            for (int nj = 0; nj < 6; nj++)
                #pragma unroll
                for (int r = 0; r < 4; r++)
                    a[nj][r] += rsrc[(nj * 4 + r) * 128 + slot * 32 + lane];

            #pragma unroll
            for (int hr = 0; hr < 2; hr++) {
                const int m = mbase + 16 * mi + (lane >> 2) + 8 * hr;
                const float inv = 1.0f / (snz[m] + 1e-5f);
                const int l  = mb * TM + m;
                const int bi = l / NW, bj = l % NW;
                const size_t base = (size_t)c * XCH + (size_t)(bi * 9) * WPITCH + (size_t)(bj * 9);
                const float* xp = x + base;
                float* op = out + base;
                #pragma unroll
                for (int nj = 0; nj < 6; nj++) {
                    #pragma unroll
                    for (int e2 = 0; e2 < 2; e2++) {
                        const int n = nbase + 8 * nj + 2 * (lane & 3) + e2;
                        if (n < 81) {
                            const int ki = n / 9, kj = n % 9;
                            const float a2 = a[nj][hr * 2 + e2] * inv;
                            const float xv = xp[ki * WPITCH + kj];
                            const float o  = fmaf(a2, xv, xv);
                            op[ki * WPITCH + kj] = (o >= 0.0f) ? o : 0.2f * o;
                        }
                    }
                }
            }
        };

        if (kg == 0) epi(acc[0], redA, 0);
        else         epi(acc[1], redB, 1);
    }
}

// ---------------- launch ----------------
extern "C" void kernel_launch(void* const* d_in, const int* in_sizes, int n_in,
                              void* d_out, int out_size) {
    const float* x;
    const float* attn;
    if (in_sizes[0] == 1492992) {           // x is 1*4*72*72*72
        x = (const float*)d_in[0];
        attn = (const float*)d_in[1];
    } else {
        x = (const float*)d_in[1];
        attn = (const float*)d_in[0];
    }
    cudaFuncSetAttribute(cross_head_main,
                         cudaFuncAttributeMaxDynamicSharedMemorySize, SMEM_BYTES);
    build_b_kernel<<<512, 256>>>(x);
    cross_head_main<<<NCH * NBLK_M, 256, SMEM_BYTES>>>(attn, x, (float*)d_out);
}